// round 13
// baseline (speedup 1.0000x reference)
#include <cuda_runtime.h>
#include <cstdint>

// Shift op: x[32,64,56,56] -> out[32,576,56,56]
// out[n, c*9 + s, y, x] = x[n, c, y + s/3 - 1, x + s%3 - 1], zero-padded.
//
// R13: last unmeasured cell of the (rows-per-thread x access-width) matrix:
// 2 output rows per thread (R4's winning shape) x 256-bit ld/st (v8.b32).
// Per thread: 4 LDG.256 (rows y-1..y+2) + 8 edge scalars -> 18 STG.256.
// Same instruction counts as R4 at double the bytes/instruction.

#define N_  32
#define C_  64
#define H_  56
#define W_  56
#define W8 (W_ / 8)      // 7 float8 per row
#define H2 (H_ / 2)      // 28 row-pairs

struct F8 { uint32_t r[8]; };

__device__ __forceinline__ F8 ldg256(const float* p) {
    F8 v;
    asm volatile(
        "ld.global.nc.L2::evict_last.v8.b32 {%0,%1,%2,%3,%4,%5,%6,%7}, [%8];"
        : "=r"(v.r[0]), "=r"(v.r[1]), "=r"(v.r[2]), "=r"(v.r[3]),
          "=r"(v.r[4]), "=r"(v.r[5]), "=r"(v.r[6]), "=r"(v.r[7])
        : "l"(p));
    return v;
}
__device__ __forceinline__ void stg256(float* p, const F8& v) {
    asm volatile(
        "st.global.cs.v8.b32 [%0], {%1,%2,%3,%4,%5,%6,%7,%8};"
        :: "l"(p),
           "r"(v.r[0]), "r"(v.r[1]), "r"(v.r[2]), "r"(v.r[3]),
           "r"(v.r[4]), "r"(v.r[5]), "r"(v.r[6]), "r"(v.r[7])
        : "memory");
}

__global__ __launch_bounds__(256) void shift_kernel(
    const float* __restrict__ in, float* __restrict__ out, int total)
{
    int idx = blockIdx.x * blockDim.x + threadIdx.x;
    if (idx >= total) return;

    // idx -> (nc, y2, x8);  y = 2*y2
    int x8 = idx % W8;
    int t  = idx / W8;
    int y2 = t % H2;
    int nc = t / H2;
    int y  = y2 * 2;

    int x0 = x8 * 8;
    const float* plane = in + (long long)nc * (H_ * W_);

    // rows y-1 .. y+2
    F8       v[4];
    uint32_t lft[4], rgt[4];
    #pragma unroll
    for (int r = 0; r < 4; r++) {
        int sy = y + r - 1;
        if ((unsigned)sy < (unsigned)H_) {
            const float* row = plane + sy * W_;
            v[r] = ldg256(row + x0);
            lft[r] = (x0 > 0)      ? __float_as_uint(__ldg(row + x0 - 1)) : 0u;
            rgt[r] = (x0 + 8 < W_) ? __float_as_uint(__ldg(row + x0 + 8)) : 0u;
        } else {
            #pragma unroll
            for (int i = 0; i < 8; i++) v[r].r[i] = 0u;
            lft[r] = 0u;
            rgt[r] = 0u;
        }
    }

    // out base (floats) for (nc, s=0, y, x8)
    float* obase = out + ((long long)nc * 9) * (H_ * W_) + y * W_ + x0;
    const int sstride = H_ * W_;   // one s-plane in floats

    #pragma unroll
    for (int dy = 0; dy < 3; dy++) {
        #pragma unroll
        for (int r = 0; r < 2; r++) {
            const F8& b = v[dy + r];
            F8 a, c;
            a.r[0] = lft[dy + r];
            #pragma unroll
            for (int i = 0; i < 7; i++) { a.r[i + 1] = b.r[i]; c.r[i] = b.r[i + 1]; }
            c.r[7] = rgt[dy + r];
            float* o = obase + r * W_;
            stg256(o + (dy * 3 + 0) * sstride, a);
            stg256(o + (dy * 3 + 1) * sstride, b);
            stg256(o + (dy * 3 + 2) * sstride, c);
        }
    }
}

extern "C" void kernel_launch(void* const* d_in, const int* in_sizes, int n_in,
                              void* d_out, int out_size) {
    const float* x = (const float*)d_in[0];
    float* out = (float*)d_out;
    int total = N_ * C_ * H2 * W8;   // 401,408 threads
    int threads = 256;
    int blocks = (total + threads - 1) / threads;
    shift_kernel<<<blocks, threads>>>(x, out, total);
}

// round 15
// speedup vs baseline: 1.1502x; 1.1502x over previous
#include <cuda_runtime.h>
#include <cstdint>

// Shift op: x[32,64,56,56] -> out[32,576,56,56]
// out[n, c*9 + s, y, x] = x[n, c, y + s/3 - 1, x + s%3 - 1], zero-padded.
//
// FINAL (= R7, the measured optimum over the full design matrix):
//  - 2 output rows per thread: 4 aligned float4 loads + 8 edge scalars
//    feed 18 independent STG.128 (the sweet spot of the U-shaped
//    amortization curve; 1 row is LSU-issue bound, 4 rows is
//    latency/occupancy bound).
//  - loads: ld.global.nc.L2::cache_hint + fractional evict_last policy
//    (input 26MB stays L2-resident across its 9 rereads).
//  - stores: st.global.cs (evict-first; 231MB write stream doesn't churn L2).
// All measured variants (bulk-async staging, 256-bit v8 accesses, higher
// occupancy, plane-sequential write order, 4-row amortization) were neutral
// or worse: the kernel sits at the HBM3e write-stream wall (~5.1 TB/s
// effective for ~90%-write traffic).

#define N_  32
#define C_  64
#define H_  56
#define W_  56
#define W4 (W_ / 4)      // 14
#define H2 (H_ / 2)      // 28 row-pairs

__device__ __forceinline__ uint64_t mk_policy() {
    uint64_t p;
    asm("createpolicy.fractional.L2::evict_last.b64 %0, 1.0;" : "=l"(p));
    return p;
}

__device__ __forceinline__ float4 ldg_el4(const float* p, uint64_t pol) {
    float4 v;
    asm volatile("ld.global.nc.L2::cache_hint.v4.f32 {%0,%1,%2,%3}, [%4], %5;"
                 : "=f"(v.x), "=f"(v.y), "=f"(v.z), "=f"(v.w)
                 : "l"(p), "l"(pol));
    return v;
}
__device__ __forceinline__ float ldg_el1(const float* p, uint64_t pol) {
    float v;
    asm volatile("ld.global.nc.L2::cache_hint.f32 %0, [%1], %2;"
                 : "=f"(v) : "l"(p), "l"(pol));
    return v;
}

__global__ __launch_bounds__(256) void shift_kernel(
    const float* __restrict__ in, float* __restrict__ out, int total)
{
    int idx = blockIdx.x * blockDim.x + threadIdx.x;
    if (idx >= total) return;

    const uint64_t pol = mk_policy();

    // idx -> (nc, y2, x4);  y = 2*y2
    int x4 = idx % W4;
    int t  = idx / W4;
    int y2 = t % H2;
    int nc = t / H2;
    int y  = y2 * 2;

    int x0 = x4 * 4;
    const float* plane = in + (long long)nc * (H_ * W_);

    // rows y-1 .. y+2
    float4 v[4];
    float  lft[4], rgt[4];
    #pragma unroll
    for (int r = 0; r < 4; r++) {
        int sy = y + r - 1;
        if ((unsigned)sy < (unsigned)H_) {
            const float* row = plane + sy * W_;
            v[r]   = ldg_el4(row + x0, pol);
            lft[r] = (x0 > 0)      ? ldg_el1(row + x0 - 1, pol) : 0.f;
            rgt[r] = (x0 + 4 < W_) ? ldg_el1(row + x0 + 4, pol) : 0.f;
        } else {
            v[r]   = make_float4(0.f, 0.f, 0.f, 0.f);
            lft[r] = 0.f;
            rgt[r] = 0.f;
        }
    }

    // out float4 base for (nc, s=0, y, x4)
    float4* obase = reinterpret_cast<float4*>(out)
                    + ((long long)nc * 9) * (H_ * W4) + y * W4 + x4;
    const int sstride = H_ * W4;   // one s-plane in float4s

    #pragma unroll
    for (int dy = 0; dy < 3; dy++) {
        #pragma unroll
        for (int r = 0; r < 2; r++) {
            float4 b = v[dy + r];                               // src row y+r+dy-1
            float4 a = make_float4(lft[dy + r], b.x, b.y, b.z); // dx = 0
            float4 c = make_float4(b.y, b.z, b.w, rgt[dy + r]); // dx = 2
            float4* o = obase + r * W4;
            __stcs(o + (dy * 3 + 0) * sstride, a);
            __stcs(o + (dy * 3 + 1) * sstride, b);
            __stcs(o + (dy * 3 + 2) * sstride, c);
        }
    }
}

extern "C" void kernel_launch(void* const* d_in, const int* in_sizes, int n_in,
                              void* d_out, int out_size) {
    const float* x = (const float*)d_in[0];
    float* out = (float*)d_out;
    int total = N_ * C_ * H2 * W4;   // 802,816 threads
    int threads = 256;
    int blocks = (total + threads - 1) / threads;
    shift_kernel<<<blocks, threads>>>(x, out, total);
}

// round 16
// speedup vs baseline: 1.1511x; 1.0008x over previous
#include <cuda_runtime.h>
#include <cstdint>

// Shift op: x[32,64,56,56] -> out[32,576,56,56]
// out[n, c*9 + s, y, x] = x[n, c, y + s/3 - 1, x + s%3 - 1], zero-padded.
//
// R16 = R7 (converged optimum: 2 rows/thread, float4, evict-last loads,
// .cs stores) with two micro-tweaks:
//  - stores regrouped plane-major: for each s, rows y and y+1 are issued
//    back-to-back (they are contiguous 448B in GMEM -> merged write bursts).
//  - block = 512 (same per-thread code, fewer blocks).

#define N_  32
#define C_  64
#define H_  56
#define W_  56
#define W4 (W_ / 4)      // 14
#define H2 (H_ / 2)      // 28 row-pairs

__device__ __forceinline__ uint64_t mk_policy() {
    uint64_t p;
    asm("createpolicy.fractional.L2::evict_last.b64 %0, 1.0;" : "=l"(p));
    return p;
}

__device__ __forceinline__ float4 ldg_el4(const float* p, uint64_t pol) {
    float4 v;
    asm volatile("ld.global.nc.L2::cache_hint.v4.f32 {%0,%1,%2,%3}, [%4], %5;"
                 : "=f"(v.x), "=f"(v.y), "=f"(v.z), "=f"(v.w)
                 : "l"(p), "l"(pol));
    return v;
}
__device__ __forceinline__ float ldg_el1(const float* p, uint64_t pol) {
    float v;
    asm volatile("ld.global.nc.L2::cache_hint.f32 %0, [%1], %2;"
                 : "=f"(v) : "l"(p), "l"(pol));
    return v;
}

__global__ __launch_bounds__(512) void shift_kernel(
    const float* __restrict__ in, float* __restrict__ out, int total)
{
    int idx = blockIdx.x * blockDim.x + threadIdx.x;
    if (idx >= total) return;

    const uint64_t pol = mk_policy();

    // idx -> (nc, y2, x4);  y = 2*y2
    int x4 = idx % W4;
    int t  = idx / W4;
    int y2 = t % H2;
    int nc = t / H2;
    int y  = y2 * 2;

    int x0 = x4 * 4;
    const float* plane = in + (long long)nc * (H_ * W_);

    // rows y-1 .. y+2
    float4 v[4];
    float  lft[4], rgt[4];
    #pragma unroll
    for (int r = 0; r < 4; r++) {
        int sy = y + r - 1;
        if ((unsigned)sy < (unsigned)H_) {
            const float* row = plane + sy * W_;
            v[r]   = ldg_el4(row + x0, pol);
            lft[r] = (x0 > 0)      ? ldg_el1(row + x0 - 1, pol) : 0.f;
            rgt[r] = (x0 + 4 < W_) ? ldg_el1(row + x0 + 4, pol) : 0.f;
        } else {
            v[r]   = make_float4(0.f, 0.f, 0.f, 0.f);
            lft[r] = 0.f;
            rgt[r] = 0.f;
        }
    }

    // out float4 base for (nc, s=0, y, x4)
    float4* obase = reinterpret_cast<float4*>(out)
                    + ((long long)nc * 9) * (H_ * W4) + y * W4 + x4;
    const int sstride = H_ * W4;   // one s-plane in float4s

    // Plane-major store order: per (dy,dx) plane, both rows back-to-back
    // (rows y and y+1 are 224B apart -> each pair is a contiguous-ish burst).
    #pragma unroll
    for (int dy = 0; dy < 3; dy++) {
        float4* op0 = obase + (dy * 3 + 0) * sstride;
        float4* op1 = obase + (dy * 3 + 1) * sstride;
        float4* op2 = obase + (dy * 3 + 2) * sstride;

        float4 b0 = v[dy],     b1 = v[dy + 1];
        float4 a0 = make_float4(lft[dy],     b0.x, b0.y, b0.z);
        float4 a1 = make_float4(lft[dy + 1], b1.x, b1.y, b1.z);
        float4 c0 = make_float4(b0.y, b0.z, b0.w, rgt[dy]);
        float4 c1 = make_float4(b1.y, b1.z, b1.w, rgt[dy + 1]);

        __stcs(op0,      a0);  __stcs(op0 + W4, a1);   // dx=0, rows y,y+1
        __stcs(op1,      b0);  __stcs(op1 + W4, b1);   // dx=1
        __stcs(op2,      c0);  __stcs(op2 + W4, c1);   // dx=2
    }
}

extern "C" void kernel_launch(void* const* d_in, const int* in_sizes, int n_in,
                              void* d_out, int out_size) {
    const float* x = (const float*)d_in[0];
    float* out = (float*)d_out;
    int total = N_ * C_ * H2 * W4;   // 802,816 threads
    int threads = 512;
    int blocks = (total + threads - 1) / threads;
    shift_kernel<<<blocks, threads>>>(x, out, total);
}